// round 12
// baseline (speedup 1.0000x reference)
#include <cuda_runtime.h>
#include <cuda_bf16.h>

// PixCorr: mean over rows of per-row Pearson correlation between
// preds[n,:] and targets[n,:], each row D = 3*256*256 = 196608 fp32.
// Pure HBM-streaming (~402 MB read, measured pattern ceiling ~6.75 TB/s).
//
// Structure: the proven R2/R11 streaming kernel (256 blocks x 1024 threads,
// one row per block, compile-time 48-iteration float4 loop) with the fused
// last-block epilogue. R12 change: loads use __ldcs (streaming / evict-first
// cache hint) -- the 402 MB stream is strictly read-once against a 126 MB
// L2, so lines are dead after first use; evict-first keeps the miss stream
// clean. No other change.

static constexpr int NROWS   = 256;
static constexpr int D_ELEMS = 3 * 256 * 256;       // 196608
static constexpr int D4      = D_ELEMS / 4;         // 49152 float4 per row
static constexpr int TPB     = 1024;                // 48 iters/thread

// Scratch (device allocation forbidden). g_done is reset by the elected
// last block at the end of every call.
__device__ float        g_corr[NROWS];
__device__ unsigned int g_done;

__global__ void __launch_bounds__(TPB, 2)
pixcorr_fused_kernel(const float* __restrict__ preds,
                     const float* __restrict__ targets,
                     float* __restrict__ out)
{
    const int row = blockIdx.x;
    const float4* __restrict__ zp =
        reinterpret_cast<const float4*>(targets) + (size_t)row * D4;
    const float4* __restrict__ bp =
        reinterpret_cast<const float4*>(preds) + (size_t)row * D4;

    float sz = 0.f, sb = 0.f, szz = 0.f, sbb = 0.f, szb = 0.f;

    // 48 iterations per thread, compile-time trip count; unroll 4 so ptxas
    // front-batches the LDG.128s (high MLP -> DRAM latency fully hidden).
    // __ldcs: streaming loads, evict-first in L1/L2 (read-once data).
    #pragma unroll 4
    for (int i = threadIdx.x; i < D4; i += TPB) {
        const float4 zv = __ldcs(zp + i);
        const float4 bv = __ldcs(bp + i);
        sz  += (zv.x + zv.y) + (zv.z + zv.w);
        sb  += (bv.x + bv.y) + (bv.z + bv.w);
        szz += zv.x * zv.x + zv.y * zv.y + zv.z * zv.z + zv.w * zv.w;
        sbb += bv.x * bv.x + bv.y * bv.y + bv.z * bv.z + bv.w * bv.w;
        szb += zv.x * bv.x + zv.y * bv.y + zv.z * bv.z + zv.w * bv.w;
    }

    // Warp-level reduction of all 5 accumulators.
    #pragma unroll
    for (int o = 16; o > 0; o >>= 1) {
        sz  += __shfl_xor_sync(0xffffffffu, sz,  o);
        sb  += __shfl_xor_sync(0xffffffffu, sb,  o);
        szz += __shfl_xor_sync(0xffffffffu, szz, o);
        sbb += __shfl_xor_sync(0xffffffffu, sbb, o);
        szb += __shfl_xor_sync(0xffffffffu, szb, o);
    }

    __shared__ float sm[5][32];
    const int warp = threadIdx.x >> 5;
    const int lane = threadIdx.x & 31;
    if (lane == 0) {
        sm[0][warp] = sz;
        sm[1][warp] = sb;
        sm[2][warp] = szz;
        sm[3][warp] = sbb;
        sm[4][warp] = szb;
    }
    __syncthreads();

    if (warp == 0) {
        sz  = sm[0][lane];
        sb  = sm[1][lane];
        szz = sm[2][lane];
        sbb = sm[3][lane];
        szb = sm[4][lane];
        #pragma unroll
        for (int o = 16; o > 0; o >>= 1) {
            sz  += __shfl_xor_sync(0xffffffffu, sz,  o);
            sb  += __shfl_xor_sync(0xffffffffu, sb,  o);
            szz += __shfl_xor_sync(0xffffffffu, szz, o);
            sbb += __shfl_xor_sync(0xffffffffu, sbb, o);
            szb += __shfl_xor_sync(0xffffffffu, szb, o);
        }
        if (lane == 0) {
            const float invD = 1.0f / (float)D_ELEMS;
            const float num  = szb - sz * sb * invD;
            const float vz   = fmaxf(szz - sz * sz * invD, 0.0f);
            const float vb   = fmaxf(sbb - sb * sb * invD, 0.0f);
            const float den  = sqrtf(vz) * sqrtf(vb) + 1e-6f;
            g_corr[row] = num / den;
        }
    }

    // ── Last-block-done election (fused second stage) ─────────────────────
    __shared__ bool is_last;
    __syncthreads();                     // g_corr store issued block-wide
    if (threadIdx.x == 0) {
        __threadfence();                 // publish g_corr[row] GPU-wide
        unsigned int old = atomicAdd(&g_done, 1u);
        is_last = (old == NROWS - 1);
    }
    __syncthreads();
    if (!is_last) return;

    // ── Final mean over 256 rows (L2-resident reads; ~0.5us) ──────────────
    {
        float v = (threadIdx.x < NROWS) ? g_corr[threadIdx.x] : 0.0f;
        #pragma unroll
        for (int o = 16; o > 0; o >>= 1)
            v += __shfl_xor_sync(0xffffffffu, v, o);
        if (lane == 0) sm[0][warp] = v;
        __syncthreads();
        if (threadIdx.x < 8) {
            float t = sm[0][threadIdx.x];
            #pragma unroll
            for (int o = 4; o > 0; o >>= 1)
                t += __shfl_xor_sync(0x000000ffu, t, o);
            if (threadIdx.x == 0) {
                out[0] = t * (1.0f / (float)NROWS);
                g_done = 0;              // reset for next graph replay
            }
        }
    }
}

extern "C" void kernel_launch(void* const* d_in, const int* in_sizes, int n_in,
                              void* d_out, int out_size)
{
    const float* preds   = (const float*)d_in[0];
    const float* targets = (const float*)d_in[1];
    float* out = (float*)d_out;

    pixcorr_fused_kernel<<<NROWS, TPB>>>(preds, targets, out);
}

// round 15
// speedup vs baseline: 1.0015x; 1.0015x over previous
#include <cuda_runtime.h>
#include <cuda_bf16.h>

// PixCorr: mean over rows of per-row Pearson correlation between
// preds[n,:] and targets[n,:], each row D = 3*256*256 = 196608 fp32.
// Pure HBM-streaming (~402 MB read, measured pattern ceiling ~6.75 TB/s).
//
// Final configuration (empirical optimum across R2-R12 experiments):
//   - 256 blocks x 1024 threads, one row per block, occ 2/SM, 32 regs.
//   - Compile-time 48-iteration float4 loop, unroll 4 -> ptxas front-batches
//     LDG.128s, DRAM latency fully hidden (6.55+ TB/s measured).
//   - Default cache policy (evict-first __ldcs measured SLOWER: 63.7 vs 62.3).
//   - Fused last-block epilogue replaces a second launch (saves 4.35us;
//     measured win in R11). Election counter self-resets -> graph-replayable.
// All restructures (finer chunks, dynamic work queue, perfectly balanced
// spans) measured 5-10% WORSE streaming BW; do not touch the loop.

static constexpr int NROWS   = 256;
static constexpr int D_ELEMS = 3 * 256 * 256;       // 196608
static constexpr int D4      = D_ELEMS / 4;         // 49152 float4 per row
static constexpr int TPB     = 1024;                // 48 iters/thread

// Scratch (device allocation forbidden). g_done is reset by the elected
// last block at the end of every call.
__device__ float        g_corr[NROWS];
__device__ unsigned int g_done;

__global__ void __launch_bounds__(TPB, 2)
pixcorr_fused_kernel(const float* __restrict__ preds,
                     const float* __restrict__ targets,
                     float* __restrict__ out)
{
    const int row = blockIdx.x;
    const float4* __restrict__ zp =
        reinterpret_cast<const float4*>(targets) + (size_t)row * D4;
    const float4* __restrict__ bp =
        reinterpret_cast<const float4*>(preds) + (size_t)row * D4;

    float sz = 0.f, sb = 0.f, szz = 0.f, sbb = 0.f, szb = 0.f;

    // 48 iterations per thread, compile-time trip count; unroll 4 so ptxas
    // front-batches the LDG.128s (high MLP -> DRAM latency fully hidden).
    #pragma unroll 4
    for (int i = threadIdx.x; i < D4; i += TPB) {
        const float4 zv = zp[i];
        const float4 bv = bp[i];
        sz  += (zv.x + zv.y) + (zv.z + zv.w);
        sb  += (bv.x + bv.y) + (bv.z + bv.w);
        szz += zv.x * zv.x + zv.y * zv.y + zv.z * zv.z + zv.w * zv.w;
        sbb += bv.x * bv.x + bv.y * bv.y + bv.z * bv.z + bv.w * bv.w;
        szb += zv.x * bv.x + zv.y * bv.y + zv.z * bv.z + zv.w * bv.w;
    }

    // Warp-level reduction of all 5 accumulators.
    #pragma unroll
    for (int o = 16; o > 0; o >>= 1) {
        sz  += __shfl_xor_sync(0xffffffffu, sz,  o);
        sb  += __shfl_xor_sync(0xffffffffu, sb,  o);
        szz += __shfl_xor_sync(0xffffffffu, szz, o);
        sbb += __shfl_xor_sync(0xffffffffu, sbb, o);
        szb += __shfl_xor_sync(0xffffffffu, szb, o);
    }

    __shared__ float sm[5][32];
    const int warp = threadIdx.x >> 5;
    const int lane = threadIdx.x & 31;
    if (lane == 0) {
        sm[0][warp] = sz;
        sm[1][warp] = sb;
        sm[2][warp] = szz;
        sm[3][warp] = sbb;
        sm[4][warp] = szb;
    }
    __syncthreads();

    if (warp == 0) {
        sz  = sm[0][lane];
        sb  = sm[1][lane];
        szz = sm[2][lane];
        sbb = sm[3][lane];
        szb = sm[4][lane];
        #pragma unroll
        for (int o = 16; o > 0; o >>= 1) {
            sz  += __shfl_xor_sync(0xffffffffu, sz,  o);
            sb  += __shfl_xor_sync(0xffffffffu, sb,  o);
            szz += __shfl_xor_sync(0xffffffffu, szz, o);
            sbb += __shfl_xor_sync(0xffffffffu, sbb, o);
            szb += __shfl_xor_sync(0xffffffffu, szb, o);
        }
        if (lane == 0) {
            const float invD = 1.0f / (float)D_ELEMS;
            const float num  = szb - sz * sb * invD;
            const float vz   = fmaxf(szz - sz * sz * invD, 0.0f);
            const float vb   = fmaxf(sbb - sb * sb * invD, 0.0f);
            const float den  = sqrtf(vz) * sqrtf(vb) + 1e-6f;
            g_corr[row] = num / den;
        }
    }

    // ── Last-block-done election (fused second stage) ─────────────────────
    __shared__ bool is_last;
    __syncthreads();                     // g_corr store issued block-wide
    if (threadIdx.x == 0) {
        __threadfence();                 // publish g_corr[row] GPU-wide
        unsigned int old = atomicAdd(&g_done, 1u);
        is_last = (old == NROWS - 1);
    }
    __syncthreads();
    if (!is_last) return;

    // ── Final mean over 256 rows (L2-resident reads; ~0.5us) ──────────────
    {
        float v = (threadIdx.x < NROWS) ? g_corr[threadIdx.x] : 0.0f;
        #pragma unroll
        for (int o = 16; o > 0; o >>= 1)
            v += __shfl_xor_sync(0xffffffffu, v, o);
        if (lane == 0) sm[0][warp] = v;
        __syncthreads();
        if (threadIdx.x < 8) {
            float t = sm[0][threadIdx.x];
            #pragma unroll
            for (int o = 4; o > 0; o >>= 1)
                t += __shfl_xor_sync(0x000000ffu, t, o);
            if (threadIdx.x == 0) {
                out[0] = t * (1.0f / (float)NROWS);
                g_done = 0;              // reset for next graph replay
            }
        }
    }
}

extern "C" void kernel_launch(void* const* d_in, const int* in_sizes, int n_in,
                              void* d_out, int out_size)
{
    const float* preds   = (const float*)d_in[0];
    const float* targets = (const float*)d_in[1];
    float* out = (float*)d_out;

    pixcorr_fused_kernel<<<NROWS, TPB>>>(preds, targets, out);
}